// round 5
// baseline (speedup 1.0000x reference)
#include <cuda_runtime.h>
#include <cstdint>
#include <math.h>

// Problem constants (from reference setup_inputs)
#define T_TOK 4096      // B*S
#define D_DIM 1024
#define F_DIM 2048
#define E_NUM 8
#define NGRP  9         // group 0 = shared expert, groups 1..8 = routed experts
#define MAXROWS (3*T_TOK)

// ---------------- device scratch ----------------
__device__ int   g_cnt[E_NUM];
__device__ int   g_fill[E_NUM];
__device__ int   g_start[NGRP];
__device__ int   g_gcnt[NGRP];
__device__ int   g_topi[T_TOK * 2];
__device__ float g_topw[T_TOK * 2];
__device__ int   g_tok[MAXROWS];
__device__ float g_wt[MAXROWS];
__device__ int   g_rowof[T_TOK * 2];
__device__ float g_H[(size_t)MAXROWS * F_DIM];
__device__ float g_Y[(size_t)MAXROWS * D_DIM];

// ---------------- helpers ----------------
__device__ __forceinline__ uint32_t f2tf(float f) {
    uint32_t u;
    asm("cvt.rna.tf32.f32 %0, %1;" : "=r"(u) : "f"(f));
    return u;
}
__device__ __forceinline__ void mma_tf32(float c[4], const uint32_t a[4],
                                         const uint32_t b[2]) {
    asm("mma.sync.aligned.m16n8k8.row.col.f32.tf32.tf32.f32 "
        "{%0,%1,%2,%3},{%4,%5,%6,%7},{%8,%9},{%0,%1,%2,%3};"
        : "+f"(c[0]), "+f"(c[1]), "+f"(c[2]), "+f"(c[3])
        : "r"(a[0]), "r"(a[1]), "r"(a[2]), "r"(a[3]), "r"(b[0]), "r"(b[1]));
}
__device__ __forceinline__ void cp16(void* smem_dst, const void* gsrc) {
    uint32_t d = (uint32_t)__cvta_generic_to_shared(smem_dst);
    asm volatile("cp.async.ca.shared.global [%0], [%1], 16;\n" ::"r"(d), "l"(gsrc));
}
#define CP_COMMIT() asm volatile("cp.async.commit_group;")
#define CP_WAIT(n)  asm volatile("cp.async.wait_group %0;" ::"n"(n))

// ---------------- small kernels ----------------
__global__ void init_kernel() {
    int i = threadIdx.x;
    if (i < E_NUM) { g_cnt[i] = 0; g_fill[i] = 0; }
}

__global__ void router_kernel(const float* __restrict__ x,
                              const float* __restrict__ Wg) {
    int warp = (blockIdx.x * blockDim.x + threadIdx.x) >> 5;
    int lane = threadIdx.x & 31;
    if (warp >= T_TOK) return;
    const float* xr = x + (size_t)warp * D_DIM;
    float acc[E_NUM];
#pragma unroll
    for (int e = 0; e < E_NUM; e++) acc[e] = 0.f;
    for (int i = 0; i < D_DIM / 32; i++) {
        int d = i * 32 + lane;
        float xv = xr[d];
        const float4* wr = (const float4*)(Wg + (size_t)d * E_NUM);
        float4 w0 = wr[0], w1 = wr[1];
        acc[0] += xv * w0.x; acc[1] += xv * w0.y;
        acc[2] += xv * w0.z; acc[3] += xv * w0.w;
        acc[4] += xv * w1.x; acc[5] += xv * w1.y;
        acc[6] += xv * w1.z; acc[7] += xv * w1.w;
    }
#pragma unroll
    for (int e = 0; e < E_NUM; e++)
#pragma unroll
        for (int o = 16; o > 0; o >>= 1)
            acc[e] += __shfl_down_sync(0xffffffffu, acc[e], o);
    if (lane == 0) {
        int b0 = -1, b1 = -1;
        float v0 = -1e30f, v1 = -1e30f;
#pragma unroll
        for (int e = 0; e < E_NUM; e++) {
            float v = acc[e];
            if (v > v0) { v1 = v0; b1 = b0; v0 = v; b0 = e; }
            else if (v > v1) { v1 = v; b1 = e; }
        }
        float w0 = 1.f / (1.f + expf(v1 - v0));
        g_topi[warp * 2 + 0] = b0; g_topw[warp * 2 + 0] = w0;
        g_topi[warp * 2 + 1] = b1; g_topw[warp * 2 + 1] = 1.f - w0;
        atomicAdd(&g_cnt[b0], 1);
        atomicAdd(&g_cnt[b1], 1);
    }
}

// fill + fused scan: every thread recomputes the tiny 8-way prefix locally
__global__ void fill_kernel() {
    int t = blockIdx.x * blockDim.x + threadIdx.x;
    if (t >= T_TOK) return;
    int st[E_NUM];
    {
        int off = T_TOK;
#pragma unroll
        for (int e = 0; e < E_NUM; e++) { st[e] = off; off += g_cnt[e]; }
    }
    if (t == 0) {           // publish group tables for the GEMMs
        g_start[0] = 0; g_gcnt[0] = T_TOK;
#pragma unroll
        for (int e = 0; e < E_NUM; e++) {
            g_start[e + 1] = st[e];
            g_gcnt[e + 1]  = g_cnt[e];
        }
    }
    g_tok[t] = t; g_wt[t] = 1.f;
#pragma unroll
    for (int j = 0; j < 2; j++) {
        int e = g_topi[t * 2 + j];
        int r = st[e] + atomicAdd(&g_fill[e], 1);
        g_tok[r] = t;
        g_wt[r]  = g_topw[t * 2 + j];
        g_rowof[t * 2 + j] = r;
    }
}

__device__ __forceinline__ float gelu_erf(float v) {
    return 0.5f * v * (1.f + erff(v * 0.70710678118654752440f));
}

// ---------------- grouped TF32 tensor-core GEMM ----------------
// 256x128 block tile (512 threads, 16 warps as 4x4, warp tile 64x32), BK=16,
// mma m16n8k8, 3-stage cp.async pipeline (wait -> sync -> issue -> compute).
#define STAGES 3
#define A_STRIDE 20
#define B_STRIDE 136
#define A_STG_FLT (256 * A_STRIDE)          // 5120 floats
#define B_STG_FLT (16 * B_STRIDE)           // 2176 floats
#define STG_FLT   (A_STG_FLT + B_STG_FLT)   // 7296 floats
#define SMEM_SZ   (STAGES * STG_FLT * 4)    // 87552 B

template<int KDIM, int NDIM, bool UP>
__global__ __launch_bounds__(512, 1)
void grouped_gemm_tf32(const float* __restrict__ X,
                       const float* __restrict__ Bexp,
                       const float* __restrict__ Bsh) {
    extern __shared__ float smem[];

    const int g   = blockIdx.z;
    const int cnt = g_gcnt[g];
    const int m0  = blockIdx.x * 256;
    if (m0 >= cnt) return;
    const int start = g_start[g];
    const int n0    = blockIdx.y * 128;

    const float* __restrict__ B =
        (g == 0) ? Bsh : (Bexp + (size_t)(g - 1) * KDIM * NDIM);
    const float* __restrict__ Asrc = UP ? X : g_H;
    float* __restrict__ Cdst = UP ? g_H : g_Y;

    const int tid  = threadIdx.x;
    const int warp = tid >> 5;
    const int lane = tid & 31;
    const int gid  = lane >> 2;   // 0..7
    const int tig  = lane & 3;    // 0..3
    const int wm   = (warp >> 2) * 64;   // 0,64,128,192
    const int wn   = (warp & 3) * 32;    // 0,32,64,96

    // --- load geometry (per BK=16 stage) ---
    // A: 256 rows x 16 floats = 1024 cp16 -> 2/thread (rows tid>>2, +128)
    const int ra  = tid >> 2;           // 0..127
    const int c4a = (tid & 3) * 4;
    // B: 16 rows x 128 floats = 512 cp16 -> 1/thread
    const int rb  = tid >> 5;           // 0..15
    const int c4b = (tid & 31) * 4;

    int gr0 = m0 + ra;        if (gr0 >= cnt) gr0 = cnt - 1;
    int gr1 = m0 + ra + 128;  if (gr1 >= cnt) gr1 = cnt - 1;
    int sr0, sr1;
    if (UP) { sr0 = g_tok[start + gr0]; sr1 = g_tok[start + gr1]; }
    else    { sr0 = start + gr0;        sr1 = start + gr1; }
    const float* pA0 = Asrc + (size_t)sr0 * KDIM + c4a;
    const float* pA1 = Asrc + (size_t)sr1 * KDIM + c4a;
    const float* pB  = B + n0 + c4b;

    float c[4][4][4];
#pragma unroll
    for (int i = 0; i < 4; i++)
#pragma unroll
        for (int j = 0; j < 4; j++)
#pragma unroll
            for (int k = 0; k < 4; k++) c[i][j][k] = 0.f;

    const int KT = KDIM / 16;

    float* As[STAGES];
    float* Bs[STAGES];
#pragma unroll
    for (int s = 0; s < STAGES; s++) {
        As[s] = smem + s * STG_FLT;
        Bs[s] = As[s] + A_STG_FLT;
    }

    // prologue: issue stages 0..STAGES-2
#pragma unroll
    for (int s = 0; s < STAGES - 1; s++) {
        const int kb = s * 16;
        cp16(&As[s][ra * A_STRIDE + c4a],         pA0 + kb);
        cp16(&As[s][(ra + 128) * A_STRIDE + c4a], pA1 + kb);
        cp16(&Bs[s][rb * B_STRIDE + c4b],         pB + (size_t)(kb + rb) * NDIM);
        CP_COMMIT();
    }

    for (int kt = 0; kt < KT; kt++) {
        CP_WAIT(STAGES - 2);     // stage kt landed
        __syncthreads();         // all threads done reading buffer being refilled

        const int kn = kt + STAGES - 1;
        if (kn < KT) {
            float* An = As[kn % STAGES];
            float* Bn = Bs[kn % STAGES];
            const int kb = kn * 16;
            cp16(&An[ra * A_STRIDE + c4a],         pA0 + kb);
            cp16(&An[(ra + 128) * A_STRIDE + c4a], pA1 + kb);
            cp16(&Bn[rb * B_STRIDE + c4b],         pB + (size_t)(kb + rb) * NDIM);
        }
        CP_COMMIT();             // uniform group count

        const float* __restrict__ Ac = As[kt % STAGES];
        const float* __restrict__ Bc = Bs[kt % STAGES];
#pragma unroll
        for (int ks = 0; ks < 2; ks++) {
            uint32_t af[4][4], bf[4][2];
            const int kb = ks * 8;
#pragma unroll
            for (int mt = 0; mt < 4; mt++) {
                int row = wm + mt * 16 + gid;
                af[mt][0] = f2tf(Ac[row * A_STRIDE + kb + tig]);
                af[mt][1] = f2tf(Ac[(row + 8) * A_STRIDE + kb + tig]);
                af[mt][2] = f2tf(Ac[row * A_STRIDE + kb + tig + 4]);
                af[mt][3] = f2tf(Ac[(row + 8) * A_STRIDE + kb + tig + 4]);
            }
#pragma unroll
            for (int nt = 0; nt < 4; nt++) {
                int col = wn + nt * 8 + gid;
                bf[nt][0] = f2tf(Bc[(kb + tig) * B_STRIDE + col]);
                bf[nt][1] = f2tf(Bc[(kb + tig + 4) * B_STRIDE + col]);
            }
#pragma unroll
            for (int mt = 0; mt < 4; mt++)
#pragma unroll
                for (int nt = 0; nt < 4; nt++)
                    mma_tf32(c[mt][nt], af[mt], bf[nt]);
        }
    }

    // ---------------- epilogue ----------------
#pragma unroll
    for (int mt = 0; mt < 4; mt++) {
        int r0 = m0 + wm + mt * 16 + gid;
        int r1 = r0 + 8;
        float w0 = 1.f, w1 = 1.f;
        if (!UP) {
            if (r0 < cnt) w0 = g_wt[start + r0];
            if (r1 < cnt) w1 = g_wt[start + r1];
        }
#pragma unroll
        for (int nt = 0; nt < 4; nt++) {
            int col = n0 + wn + nt * 8 + tig * 2;
            if (r0 < cnt) {
                float2 v;
                if (UP) { v.x = gelu_erf(c[mt][nt][0]); v.y = gelu_erf(c[mt][nt][1]); }
                else    { v.x = c[mt][nt][0] * w0;      v.y = c[mt][nt][1] * w0; }
                *(float2*)(Cdst + (size_t)(start + r0) * NDIM + col) = v;
            }
            if (r1 < cnt) {
                float2 v;
                if (UP) { v.x = gelu_erf(c[mt][nt][2]); v.y = gelu_erf(c[mt][nt][3]); }
                else    { v.x = c[mt][nt][2] * w1;      v.y = c[mt][nt][3] * w1; }
                *(float2*)(Cdst + (size_t)(start + r1) * NDIM + col) = v;
            }
        }
    }
}

// ---------------- combine ----------------
__global__ void combine_kernel(float* __restrict__ out) {
    int i = blockIdx.x * blockDim.x + threadIdx.x;
    if (i >= T_TOK * (D_DIM / 4)) return;
    int t  = i / (D_DIM / 4);
    int c4 = i - t * (D_DIM / 4);
    int r0 = g_rowof[t * 2 + 0];
    int r1 = g_rowof[t * 2 + 1];
    float4 s = ((const float4*)(g_Y + (size_t)t  * D_DIM))[c4];
    float4 a = ((const float4*)(g_Y + (size_t)r0 * D_DIM))[c4];
    float4 b = ((const float4*)(g_Y + (size_t)r1 * D_DIM))[c4];
    float4 o;
    o.x = s.x + a.x + b.x;
    o.y = s.y + a.y + b.y;
    o.z = s.z + a.z + b.z;
    o.w = s.w + a.w + b.w;
    ((float4*)out)[i] = o;
}

// ---------------- launcher ----------------
extern "C" void kernel_launch(void* const* d_in, const int* in_sizes, int n_in,
                              void* d_out, int out_size) {
    const float* x  = (const float*)d_in[0];
    const float* Wg = (const float*)d_in[1];
    const float* Wu = (const float*)d_in[2];
    const float* Wd = (const float*)d_in[3];
    const float* W1 = (const float*)d_in[4];
    const float* W2 = (const float*)d_in[5];
    float* out = (float*)d_out;

    cudaFuncSetAttribute(grouped_gemm_tf32<D_DIM, F_DIM, true>,
                         cudaFuncAttributeMaxDynamicSharedMemorySize, SMEM_SZ);
    cudaFuncSetAttribute(grouped_gemm_tf32<F_DIM, D_DIM, false>,
                         cudaFuncAttributeMaxDynamicSharedMemorySize, SMEM_SZ);

    init_kernel<<<1, 32>>>();
    router_kernel<<<T_TOK / 8, 256>>>(x, Wg);
    fill_kernel<<<(T_TOK + 255) / 256, 256>>>();

    // up-proj + GELU: M<=4096/group (16 x 256), N = F = 2048, K = D = 1024
    grouped_gemm_tf32<D_DIM, F_DIM, true>
        <<<dim3(T_TOK / 256, F_DIM / 128, NGRP), 512, SMEM_SZ>>>(x, Wu, W1);

    // down-proj + combine weight: N = D = 1024, K = F = 2048
    grouped_gemm_tf32<F_DIM, D_DIM, false>
        <<<dim3(T_TOK / 256, D_DIM / 128, NGRP), 512, SMEM_SZ>>>(nullptr, Wd, W2);

    combine_kernel<<<(T_TOK * (D_DIM / 4) + 255) / 256, 256>>>(out);
}

// round 6
// speedup vs baseline: 1.0184x; 1.0184x over previous
#include <cuda_runtime.h>
#include <cstdint>
#include <math.h>

// Problem constants (from reference setup_inputs)
#define T_TOK 4096      // B*S
#define D_DIM 1024
#define F_DIM 2048
#define E_NUM 8
#define NGRP  9         // group 0 = shared expert, groups 1..8 = routed experts
#define MAXROWS (3*T_TOK)

// ---------------- device scratch ----------------
__device__ int   g_cnt[E_NUM];
__device__ int   g_fill[E_NUM];
__device__ int   g_start[NGRP];
__device__ int   g_gcnt[NGRP];
__device__ int   g_topi[T_TOK * 2];
__device__ float g_topw[T_TOK * 2];
__device__ int   g_tok[MAXROWS];
__device__ float g_wt[MAXROWS];
__device__ int   g_rowof[T_TOK * 2];
__device__ float g_H[(size_t)MAXROWS * F_DIM];
__device__ float g_Y[(size_t)MAXROWS * D_DIM];

// ---------------- helpers ----------------
__device__ __forceinline__ uint32_t f2tf(float f) {
    uint32_t u;
    asm("cvt.rna.tf32.f32 %0, %1;" : "=r"(u) : "f"(f));
    return u;
}
__device__ __forceinline__ void mma_tf32(float c[4], const uint32_t a[4],
                                         const uint32_t b[2]) {
    asm("mma.sync.aligned.m16n8k8.row.col.f32.tf32.tf32.f32 "
        "{%0,%1,%2,%3},{%4,%5,%6,%7},{%8,%9},{%0,%1,%2,%3};"
        : "+f"(c[0]), "+f"(c[1]), "+f"(c[2]), "+f"(c[3])
        : "r"(a[0]), "r"(a[1]), "r"(a[2]), "r"(a[3]), "r"(b[0]), "r"(b[1]));
}
__device__ __forceinline__ void cp16(void* smem_dst, const void* gsrc) {
    uint32_t d = (uint32_t)__cvta_generic_to_shared(smem_dst);
    asm volatile("cp.async.ca.shared.global [%0], [%1], 16;\n" ::"r"(d), "l"(gsrc));
}
#define CP_COMMIT() asm volatile("cp.async.commit_group;")
#define CP_WAIT(n)  asm volatile("cp.async.wait_group %0;" ::"n"(n))

// ---------------- small kernels ----------------
__global__ void init_kernel() {
    int i = threadIdx.x;
    if (i < E_NUM) { g_cnt[i] = 0; g_fill[i] = 0; }
}

__global__ void router_kernel(const float* __restrict__ x,
                              const float* __restrict__ Wg) {
    int warp = (blockIdx.x * blockDim.x + threadIdx.x) >> 5;
    int lane = threadIdx.x & 31;
    if (warp >= T_TOK) return;
    const float* xr = x + (size_t)warp * D_DIM;
    float acc[E_NUM];
#pragma unroll
    for (int e = 0; e < E_NUM; e++) acc[e] = 0.f;
    for (int i = 0; i < D_DIM / 32; i++) {
        int d = i * 32 + lane;
        float xv = xr[d];
        const float4* wr = (const float4*)(Wg + (size_t)d * E_NUM);
        float4 w0 = wr[0], w1 = wr[1];
        acc[0] += xv * w0.x; acc[1] += xv * w0.y;
        acc[2] += xv * w0.z; acc[3] += xv * w0.w;
        acc[4] += xv * w1.x; acc[5] += xv * w1.y;
        acc[6] += xv * w1.z; acc[7] += xv * w1.w;
    }
#pragma unroll
    for (int e = 0; e < E_NUM; e++)
#pragma unroll
        for (int o = 16; o > 0; o >>= 1)
            acc[e] += __shfl_down_sync(0xffffffffu, acc[e], o);
    if (lane == 0) {
        int b0 = -1, b1 = -1;
        float v0 = -1e30f, v1 = -1e30f;
#pragma unroll
        for (int e = 0; e < E_NUM; e++) {
            float v = acc[e];
            if (v > v0) { v1 = v0; b1 = b0; v0 = v; b0 = e; }
            else if (v > v1) { v1 = v; b1 = e; }
        }
        float w0 = 1.f / (1.f + expf(v1 - v0));
        g_topi[warp * 2 + 0] = b0; g_topw[warp * 2 + 0] = w0;
        g_topi[warp * 2 + 1] = b1; g_topw[warp * 2 + 1] = 1.f - w0;
        atomicAdd(&g_cnt[b0], 1);
        atomicAdd(&g_cnt[b1], 1);
    }
}

// fill + fused scan: every thread recomputes the tiny 8-way prefix locally
__global__ void fill_kernel() {
    int t = blockIdx.x * blockDim.x + threadIdx.x;
    if (t >= T_TOK) return;
    int st[E_NUM];
    {
        int off = T_TOK;
#pragma unroll
        for (int e = 0; e < E_NUM; e++) { st[e] = off; off += g_cnt[e]; }
    }
    if (t == 0) {
        g_start[0] = 0; g_gcnt[0] = T_TOK;
#pragma unroll
        for (int e = 0; e < E_NUM; e++) {
            g_start[e + 1] = st[e];
            g_gcnt[e + 1]  = g_cnt[e];
        }
    }
    g_tok[t] = t; g_wt[t] = 1.f;
#pragma unroll
    for (int j = 0; j < 2; j++) {
        int e = g_topi[t * 2 + j];
        int r = st[e] + atomicAdd(&g_fill[e], 1);
        g_tok[r] = t;
        g_wt[r]  = g_topw[t * 2 + j];
        g_rowof[t * 2 + j] = r;
    }
}

__device__ __forceinline__ float gelu_erf(float v) {
    return 0.5f * v * (1.f + erff(v * 0.70710678118654752440f));
}

// ---------------- grouped TF32 tensor-core GEMM ----------------
// 128x64 block tile, 256 threads (8 warps as 4m x 2n, warp tile 32x32), BK=16,
// mma m16n8k8, 3-stage cp.async pipeline, 3 CTAs/SM (launch_bounds cap).
#define STAGES 3
#define A_STRIDE 20
#define B_STRIDE 72
#define A_STG_FLT (128 * A_STRIDE)          // 2560 floats
#define B_STG_FLT (16 * B_STRIDE)           // 1152 floats
#define STG_FLT   (A_STG_FLT + B_STG_FLT)   // 3712 floats
#define SMEM_SZ   (STAGES * STG_FLT * 4)    // 44544 B

template<int KDIM, int NDIM, bool UP>
__global__ __launch_bounds__(256, 3)
void grouped_gemm_tf32(const float* __restrict__ X,
                       const float* __restrict__ Bexp,
                       const float* __restrict__ Bsh) {
    extern __shared__ float smem[];

    const int g   = blockIdx.z;
    const int cnt = g_gcnt[g];
    const int m0  = blockIdx.x * 128;
    if (m0 >= cnt) return;
    const int start = g_start[g];
    const int n0    = blockIdx.y * 64;

    const float* __restrict__ B =
        (g == 0) ? Bsh : (Bexp + (size_t)(g - 1) * KDIM * NDIM);
    const float* __restrict__ Asrc = UP ? X : g_H;
    float* __restrict__ Cdst = UP ? g_H : g_Y;

    const int tid  = threadIdx.x;
    const int warp = tid >> 5;
    const int lane = tid & 31;
    const int gid  = lane >> 2;   // 0..7
    const int tig  = lane & 3;    // 0..3
    const int wm   = (warp & 3) * 32;    // 0,32,64,96
    const int wn   = (warp >> 2) * 32;   // 0,32

    // --- load geometry (per BK=16 stage) ---
    // A: 128 rows x 16 floats = 512 cp16 -> 2/thread (rows tid>>2, +64)
    const int ra  = tid >> 2;           // 0..63
    const int c4a = (tid & 3) * 4;
    // B: 16 rows x 64 floats = 256 cp16 -> 1/thread
    const int rb  = tid >> 4;           // 0..15
    const int c4b = (tid & 15) * 4;

    int gr0 = m0 + ra;       if (gr0 >= cnt) gr0 = cnt - 1;
    int gr1 = m0 + ra + 64;  if (gr1 >= cnt) gr1 = cnt - 1;
    int sr0, sr1;
    if (UP) { sr0 = g_tok[start + gr0]; sr1 = g_tok[start + gr1]; }
    else    { sr0 = start + gr0;        sr1 = start + gr1; }
    const float* pA0 = Asrc + (size_t)sr0 * KDIM + c4a;
    const float* pA1 = Asrc + (size_t)sr1 * KDIM + c4a;
    const float* pB  = B + n0 + c4b;

    float c[2][4][4];
#pragma unroll
    for (int i = 0; i < 2; i++)
#pragma unroll
        for (int j = 0; j < 4; j++)
#pragma unroll
            for (int k = 0; k < 4; k++) c[i][j][k] = 0.f;

    const int KT = KDIM / 16;

    float* As[STAGES];
    float* Bs[STAGES];
#pragma unroll
    for (int s = 0; s < STAGES; s++) {
        As[s] = smem + s * STG_FLT;
        Bs[s] = As[s] + A_STG_FLT;
    }

    // prologue: issue stages 0..1
#pragma unroll
    for (int s = 0; s < STAGES - 1; s++) {
        const int kb = s * 16;
        cp16(&As[s][ra * A_STRIDE + c4a],        pA0 + kb);
        cp16(&As[s][(ra + 64) * A_STRIDE + c4a], pA1 + kb);
        cp16(&Bs[s][rb * B_STRIDE + c4b],        pB + (size_t)(kb + rb) * NDIM);
        CP_COMMIT();
    }

    for (int kt = 0; kt < KT; kt++) {
        CP_WAIT(STAGES - 2);     // stage kt has landed
        __syncthreads();         // all warps done with buffer (kt-1)%3 compute

        const int kn = kt + STAGES - 1;
        if (kn < KT) {           // refill buffer (kt+2)%3 == (kt-1)%3 (free)
            float* An = As[kn % STAGES];
            float* Bn = Bs[kn % STAGES];
            const int kb = kn * 16;
            cp16(&An[ra * A_STRIDE + c4a],        pA0 + kb);
            cp16(&An[(ra + 64) * A_STRIDE + c4a], pA1 + kb);
            cp16(&Bn[rb * B_STRIDE + c4b],        pB + (size_t)(kb + rb) * NDIM);
        }
        CP_COMMIT();             // uniform group accounting

        const float* __restrict__ Ac = As[kt % STAGES];
        const float* __restrict__ Bc = Bs[kt % STAGES];
#pragma unroll
        for (int ks = 0; ks < 2; ks++) {
            uint32_t af[2][4], bf[4][2];
            const int kb = ks * 8;
#pragma unroll
            for (int mt = 0; mt < 2; mt++) {
                int row = wm + mt * 16 + gid;
                af[mt][0] = f2tf(Ac[row * A_STRIDE + kb + tig]);
                af[mt][1] = f2tf(Ac[(row + 8) * A_STRIDE + kb + tig]);
                af[mt][2] = f2tf(Ac[row * A_STRIDE + kb + tig + 4]);
                af[mt][3] = f2tf(Ac[(row + 8) * A_STRIDE + kb + tig + 4]);
            }
#pragma unroll
            for (int nt = 0; nt < 4; nt++) {
                int col = wn + nt * 8 + gid;
                bf[nt][0] = f2tf(Bc[(kb + tig) * B_STRIDE + col]);
                bf[nt][1] = f2tf(Bc[(kb + tig + 4) * B_STRIDE + col]);
            }
#pragma unroll
            for (int mt = 0; mt < 2; mt++)
#pragma unroll
                for (int nt = 0; nt < 4; nt++)
                    mma_tf32(c[mt][nt], af[mt], bf[nt]);
        }
    }

    // ---------------- epilogue ----------------
#pragma unroll
    for (int mt = 0; mt < 2; mt++) {
        int r0 = m0 + wm + mt * 16 + gid;
        int r1 = r0 + 8;
        float w0 = 1.f, w1 = 1.f;
        if (!UP) {
            if (r0 < cnt) w0 = g_wt[start + r0];
            if (r1 < cnt) w1 = g_wt[start + r1];
        }
#pragma unroll
        for (int nt = 0; nt < 4; nt++) {
            int col = n0 + wn + nt * 8 + tig * 2;
            if (r0 < cnt) {
                float2 v;
                if (UP) { v.x = gelu_erf(c[mt][nt][0]); v.y = gelu_erf(c[mt][nt][1]); }
                else    { v.x = c[mt][nt][0] * w0;      v.y = c[mt][nt][1] * w0; }
                *(float2*)(Cdst + (size_t)(start + r0) * NDIM + col) = v;
            }
            if (r1 < cnt) {
                float2 v;
                if (UP) { v.x = gelu_erf(c[mt][nt][2]); v.y = gelu_erf(c[mt][nt][3]); }
                else    { v.x = c[mt][nt][2] * w1;      v.y = c[mt][nt][3] * w1; }
                *(float2*)(Cdst + (size_t)(start + r1) * NDIM + col) = v;
            }
        }
    }
}

// ---------------- combine ----------------
__global__ void combine_kernel(float* __restrict__ out) {
    int i = blockIdx.x * blockDim.x + threadIdx.x;
    if (i >= T_TOK * (D_DIM / 4)) return;
    int t  = i / (D_DIM / 4);
    int c4 = i - t * (D_DIM / 4);
    int r0 = g_rowof[t * 2 + 0];
    int r1 = g_rowof[t * 2 + 1];
    float4 s = ((const float4*)(g_Y + (size_t)t  * D_DIM))[c4];
    float4 a = ((const float4*)(g_Y + (size_t)r0 * D_DIM))[c4];
    float4 b = ((const float4*)(g_Y + (size_t)r1 * D_DIM))[c4];
    float4 o;
    o.x = s.x + a.x + b.x;
    o.y = s.y + a.y + b.y;
    o.z = s.z + a.z + b.z;
    o.w = s.w + a.w + b.w;
    ((float4*)out)[i] = o;
}

// ---------------- launcher ----------------
extern "C" void kernel_launch(void* const* d_in, const int* in_sizes, int n_in,
                              void* d_out, int out_size) {
    const float* x  = (const float*)d_in[0];
    const float* Wg = (const float*)d_in[1];
    const float* Wu = (const float*)d_in[2];
    const float* Wd = (const float*)d_in[3];
    const float* W1 = (const float*)d_in[4];
    const float* W2 = (const float*)d_in[5];
    float* out = (float*)d_out;

    cudaFuncSetAttribute(grouped_gemm_tf32<D_DIM, F_DIM, true>,
                         cudaFuncAttributeMaxDynamicSharedMemorySize, SMEM_SZ);
    cudaFuncSetAttribute(grouped_gemm_tf32<F_DIM, D_DIM, false>,
                         cudaFuncAttributeMaxDynamicSharedMemorySize, SMEM_SZ);

    init_kernel<<<1, 32>>>();
    router_kernel<<<T_TOK / 8, 256>>>(x, Wg);
    fill_kernel<<<(T_TOK + 255) / 256, 256>>>();

    // up-proj + GELU: N = F = 2048 (32 tiles), K = D = 1024
    grouped_gemm_tf32<D_DIM, F_DIM, true>
        <<<dim3(T_TOK / 128, F_DIM / 64, NGRP), 256, SMEM_SZ>>>(x, Wu, W1);

    // down-proj + combine weight: N = D = 1024 (16 tiles), K = F = 2048
    grouped_gemm_tf32<F_DIM, D_DIM, false>
        <<<dim3(T_TOK / 128, D_DIM / 64, NGRP), 256, SMEM_SZ>>>(nullptr, Wd, W2);

    combine_kernel<<<(T_TOK * (D_DIM / 4) + 255) / 256, 256>>>(out);
}

// round 7
// speedup vs baseline: 1.3700x; 1.3453x over previous
#include <cuda_runtime.h>
#include <cstdint>
#include <math.h>

// Problem constants (from reference setup_inputs)
#define T_TOK 4096      // B*S
#define D_DIM 1024
#define F_DIM 2048
#define E_NUM 8
#define NGRP  9         // group 0 = shared expert, groups 1..8 = routed experts
#define MAXROWS (3*T_TOK)

// ---------------- device scratch ----------------
__device__ int   g_cnt[E_NUM];
__device__ int   g_fill[E_NUM];
__device__ int   g_start[NGRP];
__device__ int   g_gcnt[NGRP];
__device__ int   g_topi[T_TOK * 2];
__device__ float g_topw[T_TOK * 2];
__device__ int   g_tok[MAXROWS];
__device__ float g_wt[MAXROWS];
__device__ int   g_rowof[T_TOK * 2];
__device__ float g_H[(size_t)MAXROWS * F_DIM];
__device__ float g_Y[(size_t)MAXROWS * D_DIM];

// ---------------- helpers ----------------
__device__ __forceinline__ uint32_t f2tf(float f) {
    uint32_t u;
    asm("cvt.rna.tf32.f32 %0, %1;" : "=r"(u) : "f"(f));
    return u;
}
__device__ __forceinline__ void mma_tf32(float c[4], const uint32_t a[4],
                                         const uint32_t b[2]) {
    asm("mma.sync.aligned.m16n8k8.row.col.f32.tf32.tf32.f32 "
        "{%0,%1,%2,%3},{%4,%5,%6,%7},{%8,%9},{%0,%1,%2,%3};"
        : "+f"(c[0]), "+f"(c[1]), "+f"(c[2]), "+f"(c[3])
        : "r"(a[0]), "r"(a[1]), "r"(a[2]), "r"(a[3]), "r"(b[0]), "r"(b[1]));
}
__device__ __forceinline__ void cp16(void* smem_dst, const void* gsrc) {
    uint32_t d = (uint32_t)__cvta_generic_to_shared(smem_dst);
    asm volatile("cp.async.ca.shared.global [%0], [%1], 16;\n" ::"r"(d), "l"(gsrc));
}
#define CP_COMMIT() asm volatile("cp.async.commit_group;")
#define CP_WAIT(n)  asm volatile("cp.async.wait_group %0;" ::"n"(n))

// ---------------- small kernels ----------------
__global__ void init_kernel() {
    int i = threadIdx.x;
    if (i < E_NUM) { g_cnt[i] = 0; g_fill[i] = 0; }
}

__global__ void router_kernel(const float* __restrict__ x,
                              const float* __restrict__ Wg) {
    int warp = (blockIdx.x * blockDim.x + threadIdx.x) >> 5;
    int lane = threadIdx.x & 31;
    if (warp >= T_TOK) return;
    const float* xr = x + (size_t)warp * D_DIM;
    float acc[E_NUM];
#pragma unroll
    for (int e = 0; e < E_NUM; e++) acc[e] = 0.f;
    for (int i = 0; i < D_DIM / 32; i++) {
        int d = i * 32 + lane;
        float xv = xr[d];
        const float4* wr = (const float4*)(Wg + (size_t)d * E_NUM);
        float4 w0 = wr[0], w1 = wr[1];
        acc[0] += xv * w0.x; acc[1] += xv * w0.y;
        acc[2] += xv * w0.z; acc[3] += xv * w0.w;
        acc[4] += xv * w1.x; acc[5] += xv * w1.y;
        acc[6] += xv * w1.z; acc[7] += xv * w1.w;
    }
#pragma unroll
    for (int e = 0; e < E_NUM; e++)
#pragma unroll
        for (int o = 16; o > 0; o >>= 1)
            acc[e] += __shfl_down_sync(0xffffffffu, acc[e], o);
    if (lane == 0) {
        int b0 = -1, b1 = -1;
        float v0 = -1e30f, v1 = -1e30f;
#pragma unroll
        for (int e = 0; e < E_NUM; e++) {
            float v = acc[e];
            if (v > v0) { v1 = v0; b1 = b0; v0 = v; b0 = e; }
            else if (v > v1) { v1 = v; b1 = e; }
        }
        float w0 = 1.f / (1.f + expf(v1 - v0));
        g_topi[warp * 2 + 0] = b0; g_topw[warp * 2 + 0] = w0;
        g_topi[warp * 2 + 1] = b1; g_topw[warp * 2 + 1] = 1.f - w0;
        atomicAdd(&g_cnt[b0], 1);
        atomicAdd(&g_cnt[b1], 1);
    }
}

// fill + fused scan
__global__ void fill_kernel() {
    int t = blockIdx.x * blockDim.x + threadIdx.x;
    if (t >= T_TOK) return;
    int st[E_NUM];
    {
        int off = T_TOK;
#pragma unroll
        for (int e = 0; e < E_NUM; e++) { st[e] = off; off += g_cnt[e]; }
    }
    if (t == 0) {
        g_start[0] = 0; g_gcnt[0] = T_TOK;
#pragma unroll
        for (int e = 0; e < E_NUM; e++) {
            g_start[e + 1] = st[e];
            g_gcnt[e + 1]  = g_cnt[e];
        }
    }
    g_tok[t] = t; g_wt[t] = 1.f;
#pragma unroll
    for (int j = 0; j < 2; j++) {
        int e = g_topi[t * 2 + j];
        int r = st[e] + atomicAdd(&g_fill[e], 1);
        g_tok[r] = t;
        g_wt[r]  = g_topw[t * 2 + j];
        g_rowof[t * 2 + j] = r;
    }
}

__device__ __forceinline__ float gelu_erf(float v) {
    return 0.5f * v * (1.f + erff(v * 0.70710678118654752440f));
}

// ---------------- grouped TF32 tensor-core GEMM ----------------
// 128x128 block tile, 128 threads (4 warps as 2x2, warp tile 64x64), BK=16,
// mma m16n8k8, 3-stage cp.async pipeline, 2 CTAs/SM.
// Rationale: 64x64 warp tile halves A's smem re-read factor (4->2) vs 64x32,
// cutting smem read traffic/stage 48KB->32KB (the R6-measured bottleneck).
#define STAGES 3
#define A_STRIDE 20
#define B_STRIDE 136
#define A_STG_FLT (128 * A_STRIDE)          // 2560 floats
#define B_STG_FLT (16 * B_STRIDE)           // 2176 floats
#define STG_FLT   (A_STG_FLT + B_STG_FLT)   // 4736 floats
#define SMEM_SZ   (STAGES * STG_FLT * 4)    // 56832 B

template<int KDIM, int NDIM, bool UP>
__global__ __launch_bounds__(128, 2)
void grouped_gemm_tf32(const float* __restrict__ X,
                       const float* __restrict__ Bexp,
                       const float* __restrict__ Bsh) {
    extern __shared__ float smem[];

    const int g   = blockIdx.z;
    const int cnt = g_gcnt[g];
    const int m0  = blockIdx.x * 128;
    if (m0 >= cnt) return;
    const int start = g_start[g];
    const int n0    = blockIdx.y * 128;

    const float* __restrict__ B =
        (g == 0) ? Bsh : (Bexp + (size_t)(g - 1) * KDIM * NDIM);
    const float* __restrict__ Asrc = UP ? X : g_H;
    float* __restrict__ Cdst = UP ? g_H : g_Y;

    const int tid  = threadIdx.x;
    const int warp = tid >> 5;
    const int lane = tid & 31;
    const int gid  = lane >> 2;   // 0..7
    const int tig  = lane & 3;    // 0..3
    const int wm   = (warp >> 1) * 64;   // 0,64
    const int wn   = (warp & 1) * 64;    // 0,64

    // --- load geometry (per BK=16 stage, 128 threads) ---
    // A: 128 rows x 16 floats = 512 cp16 -> 4/thread (rows ra+32j)
    const int ra  = tid >> 2;           // 0..31
    const int c4a = (tid & 3) * 4;
    // B: 16 rows x 128 floats = 512 cp16 -> 4/thread (rows rb+4j)
    const int rb  = tid >> 5;           // 0..3
    const int c4b = (tid & 31) * 4;

    const float* pA[4];
#pragma unroll
    for (int j = 0; j < 4; j++) {
        int gr = m0 + ra + 32 * j;
        if (gr >= cnt) gr = cnt - 1;
        int sr = UP ? g_tok[start + gr] : (start + gr);
        pA[j] = Asrc + (size_t)sr * KDIM + c4a;
    }
    const float* pB = B + n0 + c4b;

    float c[4][8][4];
#pragma unroll
    for (int i = 0; i < 4; i++)
#pragma unroll
        for (int j = 0; j < 8; j++)
#pragma unroll
            for (int k = 0; k < 4; k++) c[i][j][k] = 0.f;

    const int KT = KDIM / 16;

    float* As[STAGES];
    float* Bs[STAGES];
#pragma unroll
    for (int s = 0; s < STAGES; s++) {
        As[s] = smem + s * STG_FLT;
        Bs[s] = As[s] + A_STG_FLT;
    }

    // prologue: issue stages 0..1
#pragma unroll
    for (int s = 0; s < STAGES - 1; s++) {
        const int kb = s * 16;
#pragma unroll
        for (int j = 0; j < 4; j++)
            cp16(&As[s][(ra + 32 * j) * A_STRIDE + c4a], pA[j] + kb);
#pragma unroll
        for (int j = 0; j < 4; j++)
            cp16(&Bs[s][(rb + 4 * j) * B_STRIDE + c4b],
                 pB + (size_t)(kb + rb + 4 * j) * NDIM);
        CP_COMMIT();
    }

    for (int kt = 0; kt < KT; kt++) {
        CP_WAIT(STAGES - 2);     // stage kt has landed
        __syncthreads();         // all warps done reading the buffer being refilled

        const int kn = kt + STAGES - 1;
        if (kn < KT) {
            float* An = As[kn % STAGES];
            float* Bn = Bs[kn % STAGES];
            const int kb = kn * 16;
#pragma unroll
            for (int j = 0; j < 4; j++)
                cp16(&An[(ra + 32 * j) * A_STRIDE + c4a], pA[j] + kb);
#pragma unroll
            for (int j = 0; j < 4; j++)
                cp16(&Bn[(rb + 4 * j) * B_STRIDE + c4b],
                     pB + (size_t)(kb + rb + 4 * j) * NDIM);
        }
        CP_COMMIT();             // uniform group accounting

        const float* __restrict__ Ac = As[kt % STAGES];
        const float* __restrict__ Bc = Bs[kt % STAGES];
#pragma unroll
        for (int ks = 0; ks < 2; ks++) {
            uint32_t af[4][4], bf[8][2];
            const int kb = ks * 8;
#pragma unroll
            for (int mt = 0; mt < 4; mt++) {
                int row = wm + mt * 16 + gid;
                af[mt][0] = f2tf(Ac[row * A_STRIDE + kb + tig]);
                af[mt][1] = f2tf(Ac[(row + 8) * A_STRIDE + kb + tig]);
                af[mt][2] = f2tf(Ac[row * A_STRIDE + kb + tig + 4]);
                af[mt][3] = f2tf(Ac[(row + 8) * A_STRIDE + kb + tig + 4]);
            }
#pragma unroll
            for (int nt = 0; nt < 8; nt++) {
                int col = wn + nt * 8 + gid;
                bf[nt][0] = f2tf(Bc[(kb + tig) * B_STRIDE + col]);
                bf[nt][1] = f2tf(Bc[(kb + tig + 4) * B_STRIDE + col]);
            }
#pragma unroll
            for (int mt = 0; mt < 4; mt++)
#pragma unroll
                for (int nt = 0; nt < 8; nt++)
                    mma_tf32(c[mt][nt], af[mt], bf[nt]);
        }
    }

    // ---------------- epilogue ----------------
#pragma unroll
    for (int mt = 0; mt < 4; mt++) {
        int r0 = m0 + wm + mt * 16 + gid;
        int r1 = r0 + 8;
        float w0 = 1.f, w1 = 1.f;
        if (!UP) {
            if (r0 < cnt) w0 = g_wt[start + r0];
            if (r1 < cnt) w1 = g_wt[start + r1];
        }
#pragma unroll
        for (int nt = 0; nt < 8; nt++) {
            int col = n0 + wn + nt * 8 + tig * 2;
            if (r0 < cnt) {
                float2 v;
                if (UP) { v.x = gelu_erf(c[mt][nt][0]); v.y = gelu_erf(c[mt][nt][1]); }
                else    { v.x = c[mt][nt][0] * w0;      v.y = c[mt][nt][1] * w0; }
                *(float2*)(Cdst + (size_t)(start + r0) * NDIM + col) = v;
            }
            if (r1 < cnt) {
                float2 v;
                if (UP) { v.x = gelu_erf(c[mt][nt][2]); v.y = gelu_erf(c[mt][nt][3]); }
                else    { v.x = c[mt][nt][2] * w1;      v.y = c[mt][nt][3] * w1; }
                *(float2*)(Cdst + (size_t)(start + r1) * NDIM + col) = v;
            }
        }
    }
}

// ---------------- combine ----------------
__global__ void combine_kernel(float* __restrict__ out) {
    int i = blockIdx.x * blockDim.x + threadIdx.x;
    if (i >= T_TOK * (D_DIM / 4)) return;
    int t  = i / (D_DIM / 4);
    int c4 = i - t * (D_DIM / 4);
    int r0 = g_rowof[t * 2 + 0];
    int r1 = g_rowof[t * 2 + 1];
    float4 s = ((const float4*)(g_Y + (size_t)t  * D_DIM))[c4];
    float4 a = ((const float4*)(g_Y + (size_t)r0 * D_DIM))[c4];
    float4 b = ((const float4*)(g_Y + (size_t)r1 * D_DIM))[c4];
    float4 o;
    o.x = s.x + a.x + b.x;
    o.y = s.y + a.y + b.y;
    o.z = s.z + a.z + b.z;
    o.w = s.w + a.w + b.w;
    ((float4*)out)[i] = o;
}

// ---------------- launcher ----------------
extern "C" void kernel_launch(void* const* d_in, const int* in_sizes, int n_in,
                              void* d_out, int out_size) {
    const float* x  = (const float*)d_in[0];
    const float* Wg = (const float*)d_in[1];
    const float* Wu = (const float*)d_in[2];
    const float* Wd = (const float*)d_in[3];
    const float* W1 = (const float*)d_in[4];
    const float* W2 = (const float*)d_in[5];
    float* out = (float*)d_out;

    cudaFuncSetAttribute(grouped_gemm_tf32<D_DIM, F_DIM, true>,
                         cudaFuncAttributeMaxDynamicSharedMemorySize, SMEM_SZ);
    cudaFuncSetAttribute(grouped_gemm_tf32<F_DIM, D_DIM, false>,
                         cudaFuncAttributeMaxDynamicSharedMemorySize, SMEM_SZ);

    init_kernel<<<1, 32>>>();
    router_kernel<<<T_TOK / 8, 256>>>(x, Wg);
    fill_kernel<<<(T_TOK + 255) / 256, 256>>>();

    // up-proj + GELU: N = F = 2048 (16 tiles), K = D = 1024
    grouped_gemm_tf32<D_DIM, F_DIM, true>
        <<<dim3(T_TOK / 128, F_DIM / 128, NGRP), 128, SMEM_SZ>>>(x, Wu, W1);

    // down-proj + combine weight: N = D = 1024 (8 tiles), K = F = 2048
    grouped_gemm_tf32<F_DIM, D_DIM, false>
        <<<dim3(T_TOK / 128, D_DIM / 128, NGRP), 128, SMEM_SZ>>>(nullptr, Wd, W2);

    combine_kernel<<<(T_TOK * (D_DIM / 4) + 255) / 256, 256>>>(out);
}